// round 12
// baseline (speedup 1.0000x reference)
#include <cuda_runtime.h>

#define N_NODES 20000
#define N_EDGES 320000
#define N_SLOTS (N_EDGES + N_NODES)   // even-aligned per-node regions
#define F_IN 6
#define HID 128
#define N_CLS 21
#define N_LAYERS 4
#define NUM_G 16
#define ZDIM 272

// ------------------------- scratch (static device globals) -------------------
__device__ float g_h[N_NODES * HID];            // node features
__device__ float g_proj[2][N_NODES * HID];      // Af (dst,f), Ad (dst,s)
__device__ float g_pair[N_NODES * HID * 2];     // interleaved (Bf, Bd) per [node][ch]
__device__ float g_agg[N_NODES * HID];          // aggregated messages
__device__ __align__(16) float g_es[N_SLOTS * NUM_G];  // pair-interleaved RBF rows
__device__ __align__(16) int g_srcs[N_SLOTS];   // src node in dst-sorted order
__device__ int   g_cnt[N_NODES];
__device__ int   g_rowptr[N_NODES + 1];
__device__ int   g_cursor[N_NODES];
__device__ float g_sum[HID], g_sq[HID];

// ------------------------- helpers ------------------------------------------
__device__ __forceinline__ float warp_sum(float v) {
#pragma unroll
    for (int o = 16; o; o >>= 1) v += __shfl_xor_sync(0xffffffffu, v, o);
    return v;
}
__device__ __forceinline__ float sigm(float z) {
    return __fdividef(1.0f, 1.0f + __expf(-z));
}
__device__ __forceinline__ float softp(float z) {
    return fmaxf(z, 0.0f) + __logf(1.0f + __expf(-fabsf(z)));
}

// packed f32x2 ops (sm_103a)
__device__ __forceinline__ unsigned long long pk2(float lo, float hi) {
    unsigned long long r;
    asm("mov.b64 %0, {%1, %2};" : "=l"(r) : "f"(lo), "f"(hi));
    return r;
}
__device__ __forceinline__ unsigned long long ffma2(unsigned long long a,
                                                    unsigned long long b,
                                                    unsigned long long c) {
    unsigned long long d;
    asm("fma.rn.f32x2 %0, %1, %2, %3;" : "=l"(d) : "l"(a), "l"(b), "l"(c));
    return d;
}
__device__ __forceinline__ unsigned long long add2(unsigned long long a,
                                                   unsigned long long b) {
    unsigned long long d;
    asm("add.rn.f32x2 %0, %1, %2;" : "=l"(d) : "l"(a), "l"(b));
    return d;
}
__device__ __forceinline__ void unpk2(unsigned long long v, float& lo, float& hi) {
    asm("mov.b64 {%0, %1}, %2;" : "=f"(lo), "=f"(hi) : "l"(v));
}

// ------------------------- setup: zero counts + node embedding ---------------
__global__ void setup_kernel(const float* __restrict__ x,
                             const float* __restrict__ W,
                             const float* __restrict__ b) {
    int idx = blockIdx.x * blockDim.x + threadIdx.x;
    if (idx < N_NODES) g_cnt[idx] = 0;
    if (idx < N_NODES * HID) {
        int n = idx >> 7, c = idx & 127;
        float acc = b[c];
#pragma unroll
        for (int k = 0; k < F_IN; k++)
            acc = fmaf(x[n * F_IN + k], W[k * HID + c], acc);
        g_h[idx] = acc;
    }
}

__global__ void count_kernel(const int* __restrict__ ei) {
    int e = blockIdx.x * blockDim.x + threadIdx.x;
    if (e < N_EDGES) atomicAdd(&g_cnt[ei[N_EDGES + e]], 1);
}

// single-block exclusive scan of EVEN-PADDED g_cnt -> g_rowptr (+ cursor copy)
__global__ void scan_kernel() {
    __shared__ int warp_sums[32];
    __shared__ int s_carry;
    int tid = threadIdx.x, lane = tid & 31, wid = tid >> 5;
    if (tid == 0) s_carry = 0;
    __syncthreads();
    for (int base = 0; base < N_NODES; base += 1024) {
        int i = base + tid;
        int v = (i < N_NODES) ? ((g_cnt[i] + 1) & ~1) : 0;   // pad to even
        int x = v;
#pragma unroll
        for (int off = 1; off < 32; off <<= 1) {
            int y = __shfl_up_sync(0xffffffffu, x, off);
            if (lane >= off) x += y;
        }
        if (lane == 31) warp_sums[wid] = x;
        __syncthreads();
        if (wid == 0) {
            int s = warp_sums[lane];
#pragma unroll
            for (int off = 1; off < 32; off <<= 1) {
                int y = __shfl_up_sync(0xffffffffu, s, off);
                if (lane >= off) s += y;
            }
            warp_sums[lane] = s;
        }
        __syncthreads();
        int woff = (wid > 0) ? warp_sums[wid - 1] : 0;
        int incl = x + woff;
        if (i < N_NODES) {
            int ex = s_carry + incl - v;
            g_rowptr[i] = ex;
            g_cursor[i] = ex;
        }
        __syncthreads();
        if (tid == 0) s_carry += warp_sums[31];
        __syncthreads();
    }
    if (threadIdx.x == 0) g_rowptr[N_NODES] = s_carry;
}

// RBF expansion + scatter, PAIR-INTERLEAVED: slot p, gaussian k lives at
// g_es[(p>>1)*32 + 2k + (p&1)]  ->  one LDG.128 in the edge loop yields two
// (e_k[2j], e_k[2j+1]) packed multipliers.
__global__ void rbf_scatter_kernel(const float* __restrict__ dist,
                                   const int* __restrict__ ei) {
    int e = blockIdx.x * blockDim.x + threadIdx.x;
    if (e >= N_EDGES) return;
    float d = dist[e];
    float ev[NUM_G];
#pragma unroll
    for (int k = 0; k < NUM_G; k++) {
        float t = d - (float)k * (8.0f / 15.0f);
        ev[k] = __expf(-1.7578125f * t * t);
    }
    int dst = ei[N_EDGES + e];
    int src = ei[e];
    int p = atomicAdd(&g_cursor[dst], 1);
    g_srcs[p] = src;
    float* o = &g_es[(p >> 1) * 32 + (p & 1)];
#pragma unroll
    for (int k = 0; k < NUM_G; k++) o[2 * k] = ev[k];
}

// ------------------------- per-layer node GEMM (128x128, BK=16, dbuf) --------
// nb: 0 -> Af (g_proj[0]), 1 -> Bf (g_pair even), 2 -> Ad (g_proj[1]), 3 -> Bd (g_pair odd)
__global__ __launch_bounds__(256, 2) void gemm_node_kernel(
    const float* __restrict__ Wf, const float* __restrict__ Ws, int layer) {
    if (blockIdx.x == 0 && blockIdx.y == 0 && threadIdx.x < HID) {
        g_sum[threadIdx.x] = 0.0f;
        g_sq[threadIdx.x] = 0.0f;
    }

    int nb = blockIdx.y;
    const float* B = ((nb < 2) ? Wf : Ws) + layer * ZDIM * HID + (nb & 1) * HID * HID;
    int m0 = blockIdx.x * 128;

    __shared__ float As[2][16][132];
    __shared__ float Bs[2][16][128];

    int tid = threadIdx.x;
    int tx = tid & 15, ty = tid >> 4;

    int arow = tid & 127;
    int akq = (tid >> 7) * 8;
    int brow = tid >> 4;
    int bcol = (tid & 15) * 8;

    float acc[8][8];
#pragma unroll
    for (int i = 0; i < 8; i++)
#pragma unroll
        for (int j = 0; j < 8; j++) acc[i][j] = 0.0f;

    int gm_a = m0 + arow;
    bool a_ok = (gm_a < N_NODES);
    const float* a_ptr = &g_h[(a_ok ? gm_a : 0) * HID + akq];

    float4 pa0 = make_float4(0.f, 0.f, 0.f, 0.f), pa1 = pa0;
    if (a_ok) { pa0 = *(const float4*)&a_ptr[0]; pa1 = *(const float4*)&a_ptr[4]; }
    float4 pb0 = *(const float4*)&B[brow * HID + bcol];
    float4 pb1 = *(const float4*)&B[brow * HID + bcol + 4];
    {
        As[0][akq + 0][arow] = pa0.x; As[0][akq + 1][arow] = pa0.y;
        As[0][akq + 2][arow] = pa0.z; As[0][akq + 3][arow] = pa0.w;
        As[0][akq + 4][arow] = pa1.x; As[0][akq + 5][arow] = pa1.y;
        As[0][akq + 6][arow] = pa1.z; As[0][akq + 7][arow] = pa1.w;
        *(float4*)&Bs[0][brow][bcol] = pb0;
        *(float4*)&Bs[0][brow][bcol + 4] = pb1;
    }
    __syncthreads();

#pragma unroll
    for (int s = 0; s < 8; s++) {
        int buf = s & 1;
        if (s < 7) {
            int k0 = (s + 1) * 16;
            pa0 = make_float4(0.f, 0.f, 0.f, 0.f); pa1 = pa0;
            if (a_ok) {
                pa0 = *(const float4*)&a_ptr[k0];
                pa1 = *(const float4*)&a_ptr[k0 + 4];
            }
            pb0 = *(const float4*)&B[(k0 + brow) * HID + bcol];
            pb1 = *(const float4*)&B[(k0 + brow) * HID + bcol + 4];
        }
#pragma unroll
        for (int k = 0; k < 16; k++) {
            float4 a0 = *(const float4*)&As[buf][k][ty * 4];
            float4 a1 = *(const float4*)&As[buf][k][64 + ty * 4];
            float4 b0 = *(const float4*)&Bs[buf][k][tx * 4];
            float4 b1 = *(const float4*)&Bs[buf][k][64 + tx * 4];
            float av[8] = {a0.x, a0.y, a0.z, a0.w, a1.x, a1.y, a1.z, a1.w};
            float bv[8] = {b0.x, b0.y, b0.z, b0.w, b1.x, b1.y, b1.z, b1.w};
#pragma unroll
            for (int i = 0; i < 8; i++)
#pragma unroll
                for (int j = 0; j < 8; j++)
                    acc[i][j] = fmaf(av[i], bv[j], acc[i][j]);
        }
        if (s < 7) {
            int nbuf = buf ^ 1;
            As[nbuf][akq + 0][arow] = pa0.x; As[nbuf][akq + 1][arow] = pa0.y;
            As[nbuf][akq + 2][arow] = pa0.z; As[nbuf][akq + 3][arow] = pa0.w;
            As[nbuf][akq + 4][arow] = pa1.x; As[nbuf][akq + 5][arow] = pa1.y;
            As[nbuf][akq + 6][arow] = pa1.z; As[nbuf][akq + 7][arow] = pa1.w;
            *(float4*)&Bs[nbuf][brow][bcol] = pb0;
            *(float4*)&Bs[nbuf][brow][bcol + 4] = pb1;
        }
        __syncthreads();
    }

    if (nb == 0 || nb == 2) {
        float* out = g_proj[nb >> 1];
#pragma unroll
        for (int i = 0; i < 4; i++) {
            int gm = m0 + ty * 4 + i;
            if (gm < N_NODES) {
                *(float4*)&out[gm * HID + tx * 4] =
                    make_float4(acc[i][0], acc[i][1], acc[i][2], acc[i][3]);
                *(float4*)&out[gm * HID + 64 + tx * 4] =
                    make_float4(acc[i][4], acc[i][5], acc[i][6], acc[i][7]);
            }
            int gm2 = m0 + 64 + ty * 4 + i;
            if (gm2 < N_NODES) {
                *(float4*)&out[gm2 * HID + tx * 4] =
                    make_float4(acc[4 + i][0], acc[4 + i][1], acc[4 + i][2], acc[4 + i][3]);
                *(float4*)&out[gm2 * HID + 64 + tx * 4] =
                    make_float4(acc[4 + i][4], acc[4 + i][5], acc[4 + i][6], acc[4 + i][7]);
            }
        }
    } else {
        float* op = g_pair + ((nb == 1) ? 0 : 1);
#pragma unroll
        for (int i = 0; i < 4; i++) {
            int gm = m0 + ty * 4 + i;
            if (gm < N_NODES) {
#pragma unroll
                for (int j = 0; j < 4; j++) {
                    op[(gm * HID + tx * 4 + j) * 2] = acc[i][j];
                    op[(gm * HID + 64 + tx * 4 + j) * 2] = acc[i][4 + j];
                }
            }
            int gm2 = m0 + 64 + ty * 4 + i;
            if (gm2 < N_NODES) {
#pragma unroll
                for (int j = 0; j < 4; j++) {
                    op[(gm2 * HID + tx * 4 + j) * 2] = acc[4 + i][j];
                    op[(gm2 * HID + 64 + tx * 4 + j) * 2] = acc[4 + i][4 + j];
                }
            }
        }
    }
}

// ------ edge aggregation: ONE node per 128-thread CTA, 2 edges/iteration.
//        f32x2 lanes = (edge0, edge1); e multipliers arrive pre-packed. ------
__global__ __launch_bounds__(128) void edge_agg_kernel(
    const float* __restrict__ Wf, const float* __restrict__ Ws,
    const float* __restrict__ bfb, const float* __restrict__ bsb, int layer) {
    const float* Wfl = Wf + layer * ZDIM * HID + 256 * HID;   // RBF rows
    const float* Wsl = Ws + layer * ZDIM * HID + 256 * HID;

    int node = blockIdx.x;
    int ch = threadIdx.x;                 // 0..127

    // packed weights (w, w) — registers, loaded once
    unsigned long long wfp[NUM_G], wsp[NUM_G];
#pragma unroll
    for (int k = 0; k < NUM_G; k++) {
        float wf = Wfl[k * HID + ch];
        float ws = Wsl[k * HID + ch];
        wfp[k] = pk2(wf, wf);
        wsp[k] = pk2(ws, ws);
    }

    const float2* PairC = ((const float2*)g_pair) + ch;   // [node][ch] -> (Bf, Bd)

    float af = g_proj[0][node * HID + ch] + bfb[layer * HID + ch];
    float as = g_proj[1][node * HID + ch] + bsb[layer * HID + ch];
    unsigned long long af2 = pk2(af, af);
    unsigned long long as2 = pk2(as, as);
    unsigned long long zz = pk2(0.0f, 0.0f);

    int start = g_rowptr[node];           // even-aligned
    int count = g_cnt[node];
    float acc = 0.0f;

    if (count > 0) {
        int p0 = start >> 1;
        int npairs = (count + 1) >> 1;
        int plast = p0 + npairs - 1;
        const int2* SP = (const int2*)g_srcs;
        const ulonglong2* EP = (const ulonglong2*)g_es;   // 8 per pair-block

        // prime gather pipeline (2 pairs deep)
        int2 sA = SP[p0];
        int2 sB = SP[min(p0 + 1, plast)];
        float2 gA0 = PairC[sA.x * HID], gA1 = PairC[sA.y * HID];
        float2 gB0 = PairC[sB.x * HID], gB1 = PairC[sB.y * HID];

        for (int jj = 0; jj < npairs; jj++) {
            int pj = p0 + jj;
            const ulonglong2* eb = &EP[pj * 8];
            // e loads for current pair: uniform LDG.128, each .x/.y is a
            // ready-made (e_k[2j], e_k[2j+1]) packed multiplier
            ulonglong2 q0 = eb[0], q1 = eb[1], q2 = eb[2], q3 = eb[3];
            ulonglong2 q4 = eb[4], q5 = eb[5], q6 = eb[6], q7 = eb[7];
            // prefetch gathers for pair jj+2
            int2 sN = SP[min(pj + 2, plast)];
            float2 gN0 = PairC[sN.x * HID], gN1 = PairC[sN.y * HID];

            // 4 independent FFMA2 chains (f-even, f-odd, s-even, s-odd)
            unsigned long long zfA = add2(af2, pk2(gA0.x, gA1.x));
            unsigned long long zsA = add2(as2, pk2(gA0.y, gA1.y));
            unsigned long long zfB = zz, zsB = zz;

            zfA = ffma2(q0.x, wfp[0], zfA);   zfB = ffma2(q0.y, wfp[1], zfB);
            zsA = ffma2(q0.x, wsp[0], zsA);   zsB = ffma2(q0.y, wsp[1], zsB);
            zfA = ffma2(q1.x, wfp[2], zfA);   zfB = ffma2(q1.y, wfp[3], zfB);
            zsA = ffma2(q1.x, wsp[2], zsA);   zsB = ffma2(q1.y, wsp[3], zsB);
            zfA = ffma2(q2.x, wfp[4], zfA);   zfB = ffma2(q2.y, wfp[5], zfB);
            zsA = ffma2(q2.x, wsp[4], zsA);   zsB = ffma2(q2.y, wsp[5], zsB);
            zfA = ffma2(q3.x, wfp[6], zfA);   zfB = ffma2(q3.y, wfp[7], zfB);
            zsA = ffma2(q3.x, wsp[6], zsA);   zsB = ffma2(q3.y, wsp[7], zsB);
            zfA = ffma2(q4.x, wfp[8], zfA);   zfB = ffma2(q4.y, wfp[9], zfB);
            zsA = ffma2(q4.x, wsp[8], zsA);   zsB = ffma2(q4.y, wsp[9], zsB);
            zfA = ffma2(q5.x, wfp[10], zfA);  zfB = ffma2(q5.y, wfp[11], zfB);
            zsA = ffma2(q5.x, wsp[10], zsA);  zsB = ffma2(q5.y, wsp[11], zsB);
            zfA = ffma2(q6.x, wfp[12], zfA);  zfB = ffma2(q6.y, wfp[13], zfB);
            zsA = ffma2(q6.x, wsp[12], zsA);  zsB = ffma2(q6.y, wsp[13], zsB);
            zfA = ffma2(q7.x, wfp[14], zfA);  zfB = ffma2(q7.y, wfp[15], zfB);
            zsA = ffma2(q7.x, wsp[14], zsA);  zsB = ffma2(q7.y, wsp[15], zsB);

            unsigned long long zf = add2(zfA, zfB);
            unsigned long long zs = add2(zsA, zsB);
            float zf0, zf1, zs0, zs1;
            unpk2(zf, zf0, zf1);
            unpk2(zs, zs0, zs1);

            acc += sigm(zf0) * softp(zs0);
            float m2 = sigm(zf1) * softp(zs1);
            bool v2 = (2 * jj + 1) < count;   // odd-degree tail mask (NaN-safe)
            acc += v2 ? m2 : 0.0f;

            // rotate gather pipeline
            gA0 = gB0; gA1 = gB1;
            gB0 = gN0; gB1 = gN1;
        }
    }
    g_agg[node * HID + ch] = acc;

    // BN statistics: fire-and-forget REDG per channel (no smem, no barriers)
    atomicAdd(&g_sum[ch], acc);
    atomicAdd(&g_sq[ch], acc * acc);
}

// ------------------------- BN + residual + LN + ReLU + residual --------------
__global__ __launch_bounds__(256) void bn_ln_kernel(
    const float* __restrict__ bn_g, const float* __restrict__ bn_b,
    const float* __restrict__ ln_g, const float* __restrict__ ln_b, int layer) {
    __shared__ __align__(16) float sA[HID];
    __shared__ __align__(16) float sB[HID];
    int tid = threadIdx.x;
    if (tid < HID) {
        const float inv = 1.0f / (float)N_NODES;
        float mu = g_sum[tid] * inv;
        float var = g_sq[tid] * inv - mu * mu;
        float rs = rsqrtf(var + 1e-5f);
        float a = rs * bn_g[layer * HID + tid];
        sA[tid] = a;
        sB[tid] = bn_b[layer * HID + tid] - mu * a;
    }
    __syncthreads();

    int warp = tid >> 5, lane = tid & 31;
    int node = blockIdx.x * 8 + warp;
    int ch0 = lane * 4;

    float4 ag = *(const float4*)&g_agg[node * HID + ch0];
    float4 h4 = *(const float4*)&g_h[node * HID + ch0];
    float4 a4 = *(const float4*)&sA[ch0];
    float4 b4 = *(const float4*)&sB[ch0];

    float c0 = fmaf(ag.x, a4.x, b4.x) + h4.x;
    float c1 = fmaf(ag.y, a4.y, b4.y) + h4.y;
    float c2 = fmaf(ag.z, a4.z, b4.z) + h4.z;
    float c3 = fmaf(ag.w, a4.w, b4.w) + h4.w;

    float s = warp_sum(c0 + c1 + c2 + c3);
    float mean = s * (1.0f / HID);
    float sq = warp_sum(c0 * c0 + c1 * c1 + c2 * c2 + c3 * c3);
    float var = sq * (1.0f / HID) - mean * mean;
    float rs = rsqrtf(var + 1e-5f);

    float4 lg = *(const float4*)&ln_g[layer * HID + ch0];
    float4 lb = *(const float4*)&ln_b[layer * HID + ch0];

    float r0 = fmaxf(fmaf((c0 - mean) * rs, lg.x, lb.x), 0.0f) + h4.x;
    float r1 = fmaxf(fmaf((c1 - mean) * rs, lg.y, lb.y), 0.0f) + h4.y;
    float r2 = fmaxf(fmaf((c2 - mean) * rs, lg.z, lb.z), 0.0f) + h4.z;
    float r3 = fmaxf(fmaf((c3 - mean) * rs, lg.w, lb.w), 0.0f) + h4.w;

    *(float4*)&g_h[node * HID + ch0] = make_float4(r0, r1, r2, r3);
}

// ------------------------- final LN + FC -------------------------------------
__global__ __launch_bounds__(256) void final_kernel(
    const float* __restrict__ lng, const float* __restrict__ lnb,
    const float* __restrict__ Wfc, const float* __restrict__ bfc,
    float* __restrict__ out) {
    int warp = threadIdx.x >> 5, lane = threadIdx.x & 31;
    int node = blockIdx.x * 8 + warp;
    int ch0 = lane * 4;

    float4 h4 = *(const float4*)&g_h[node * HID + ch0];
    float s = warp_sum(h4.x + h4.y + h4.z + h4.w);
    float mean = s * (1.0f / HID);
    float sq = warp_sum(h4.x * h4.x + h4.y * h4.y + h4.z * h4.z + h4.w * h4.w);
    float var = sq * (1.0f / HID) - mean * mean;
    float rs = rsqrtf(var + 1e-5f);

    float4 lg = *(const float4*)&lng[ch0];
    float4 lb = *(const float4*)&lnb[ch0];
    float hn0 = fmaf((h4.x - mean) * rs, lg.x, lb.x);
    float hn1 = fmaf((h4.y - mean) * rs, lg.y, lb.y);
    float hn2 = fmaf((h4.z - mean) * rs, lg.z, lb.z);
    float hn3 = fmaf((h4.w - mean) * rs, lg.w, lb.w);

#pragma unroll
    for (int j = 0; j < N_CLS; j++) {
        float p = hn0 * Wfc[(ch0 + 0) * N_CLS + j]
                + hn1 * Wfc[(ch0 + 1) * N_CLS + j]
                + hn2 * Wfc[(ch0 + 2) * N_CLS + j]
                + hn3 * Wfc[(ch0 + 3) * N_CLS + j];
        p = warp_sum(p);
        if (lane == 0) out[node * N_CLS + j] = p + bfc[j];
    }
}

// ------------------------- launch -------------------------------------------
extern "C" void kernel_launch(void* const* d_in, const int* in_sizes, int n_in,
                              void* d_out, int out_size) {
    const float* x        = (const float*)d_in[0];
    const int*   ei       = (const int*)d_in[1];
    const float* dist     = (const float*)d_in[2];
    const float* W_node   = (const float*)d_in[3];
    const float* b_node   = (const float*)d_in[4];
    const float* Wf       = (const float*)d_in[5];
    const float* bf       = (const float*)d_in[6];
    const float* Ws       = (const float*)d_in[7];
    const float* bs       = (const float*)d_in[8];
    const float* bn_g     = (const float*)d_in[9];
    const float* bn_b     = (const float*)d_in[10];
    const float* ln_g     = (const float*)d_in[11];
    const float* ln_b     = (const float*)d_in[12];
    const float* lnout_g  = (const float*)d_in[13];
    const float* lnout_b  = (const float*)d_in[14];
    const float* W_fc     = (const float*)d_in[15];
    const float* b_fc     = (const float*)d_in[16];
    float* out = (float*)d_out;

    setup_kernel<<<(N_NODES * HID + 255) / 256, 256>>>(x, W_node, b_node);   // 1
    count_kernel<<<(N_EDGES + 255) / 256, 256>>>(ei);                        // 2
    scan_kernel<<<1, 1024>>>();                                              // 3
    gemm_node_kernel<<<dim3(157, 4), 256>>>(Wf, Ws, 0);                      // 4
    rbf_scatter_kernel<<<(N_EDGES + 255) / 256, 256>>>(dist, ei);            // 5
    edge_agg_kernel<<<N_NODES, 128>>>(Wf, Ws, bf, bs, 0);                    // 6
    bn_ln_kernel<<<N_NODES / 8, 256>>>(bn_g, bn_b, ln_g, ln_b, 0);           // 7

    for (int l = 1; l < N_LAYERS; l++) {
        gemm_node_kernel<<<dim3(157, 4), 256>>>(Wf, Ws, l);
        edge_agg_kernel<<<N_NODES, 128>>>(Wf, Ws, bf, bs, l);
        bn_ln_kernel<<<N_NODES / 8, 256>>>(bn_g, bn_b, ln_g, ln_b, l);
    }

    final_kernel<<<N_NODES / 8, 256>>>(lnout_g, lnout_b, W_fc, b_fc, out);
}

// round 13
// speedup vs baseline: 1.1010x; 1.1010x over previous
#include <cuda_runtime.h>
#include <cuda_fp16.h>

#define N_NODES 20000
#define N_EDGES 320000
#define F_IN 6
#define HID 128
#define N_CLS 21
#define N_LAYERS 4
#define NUM_G 16
#define ZDIM 272

// ------------------------- scratch (static device globals) -------------------
__device__ float g_h[N_NODES * HID];            // node features
__device__ float g_proj[2][N_NODES * HID];      // Af (dst,f), Ad (dst,s)
__device__ float g_pair[N_NODES * HID * 2];     // interleaved (Bf, Bd) per [node][ch]
__device__ float g_agg[N_NODES * HID];          // aggregated messages
__device__ __half2 g_esh[N_EDGES * 8];          // RBF rows (fp16), dst-sorted
__device__ int   g_srcs[N_EDGES];               // src node in dst-sorted order
__device__ int   g_cnt[N_NODES];
__device__ int   g_rowptr[N_NODES + 1];
__device__ int   g_cursor[N_NODES];
__device__ float g_sum[HID], g_sq[HID];

// ------------------------- helpers ------------------------------------------
__device__ __forceinline__ float warp_sum(float v) {
#pragma unroll
    for (int o = 16; o; o >>= 1) v += __shfl_xor_sync(0xffffffffu, v, o);
    return v;
}
__device__ __forceinline__ float sigm(float z) {
    return __fdividef(1.0f, 1.0f + __expf(-z));
}
__device__ __forceinline__ float softp(float z) {
    return fmaxf(z, 0.0f) + __logf(1.0f + __expf(-fabsf(z)));
}

// ------------------------- setup: zero counts + node embedding ---------------
__global__ void setup_kernel(const float* __restrict__ x,
                             const float* __restrict__ W,
                             const float* __restrict__ b) {
    int idx = blockIdx.x * blockDim.x + threadIdx.x;
    if (idx < N_NODES) g_cnt[idx] = 0;
    if (idx < N_NODES * HID) {
        int n = idx >> 7, c = idx & 127;
        float acc = b[c];
#pragma unroll
        for (int k = 0; k < F_IN; k++)
            acc = fmaf(x[n * F_IN + k], W[k * HID + c], acc);
        g_h[idx] = acc;
    }
}

__global__ void count_kernel(const int* __restrict__ ei) {
    int e = blockIdx.x * blockDim.x + threadIdx.x;
    if (e < N_EDGES) atomicAdd(&g_cnt[ei[N_EDGES + e]], 1);
}

// single-block exclusive scan of g_cnt -> g_rowptr (+ cursor copy)
__global__ void scan_kernel() {
    __shared__ int warp_sums[32];
    __shared__ int s_carry;
    int tid = threadIdx.x, lane = tid & 31, wid = tid >> 5;
    if (tid == 0) s_carry = 0;
    __syncthreads();
    for (int base = 0; base < N_NODES; base += 1024) {
        int i = base + tid;
        int v = (i < N_NODES) ? g_cnt[i] : 0;
        int x = v;
#pragma unroll
        for (int off = 1; off < 32; off <<= 1) {
            int y = __shfl_up_sync(0xffffffffu, x, off);
            if (lane >= off) x += y;
        }
        if (lane == 31) warp_sums[wid] = x;
        __syncthreads();
        if (wid == 0) {
            int s = warp_sums[lane];
#pragma unroll
            for (int off = 1; off < 32; off <<= 1) {
                int y = __shfl_up_sync(0xffffffffu, s, off);
                if (lane >= off) s += y;
            }
            warp_sums[lane] = s;
        }
        __syncthreads();
        int woff = (wid > 0) ? warp_sums[wid - 1] : 0;
        int incl = x + woff;
        if (i < N_NODES) {
            int ex = s_carry + incl - v;
            g_rowptr[i] = ex;
            g_cursor[i] = ex;
        }
        __syncthreads();
        if (tid == 0) s_carry += warp_sums[31];
        __syncthreads();
    }
    if (threadIdx.x == 0) g_rowptr[N_NODES] = s_carry;
}

// RBF expansion (fp16 storage) + scatter into dst-sorted order
__global__ void rbf_scatter_kernel(const float* __restrict__ dist,
                                   const int* __restrict__ ei) {
    int e = blockIdx.x * blockDim.x + threadIdx.x;
    if (e >= N_EDGES) return;
    float d = dist[e];
    float ev[NUM_G];
#pragma unroll
    for (int k = 0; k < NUM_G; k++) {
        float t = d - (float)k * (8.0f / 15.0f);
        ev[k] = __expf(-1.7578125f * t * t);
    }
    int dst = ei[N_EDGES + e];
    int src = ei[e];
    int p = atomicAdd(&g_cursor[dst], 1);
    g_srcs[p] = src;
    __half2 h[8];
#pragma unroll
    for (int k = 0; k < 8; k++) h[k] = __floats2half2_rn(ev[2 * k], ev[2 * k + 1]);
    uint4* o = (uint4*)&g_esh[p * 8];
    uint4 u0, u1;
    u0.x = *(unsigned*)&h[0]; u0.y = *(unsigned*)&h[1];
    u0.z = *(unsigned*)&h[2]; u0.w = *(unsigned*)&h[3];
    u1.x = *(unsigned*)&h[4]; u1.y = *(unsigned*)&h[5];
    u1.z = *(unsigned*)&h[6]; u1.w = *(unsigned*)&h[7];
    o[0] = u0;
    o[1] = u1;
}

// ------------------------- per-layer node GEMM (128x128, BK=16, dbuf) --------
// nb: 0 -> Af (g_proj[0]), 1 -> Bf (g_pair even), 2 -> Ad (g_proj[1]), 3 -> Bd (g_pair odd)
__global__ __launch_bounds__(256, 2) void gemm_node_kernel(
    const float* __restrict__ Wf, const float* __restrict__ Ws, int layer) {
    if (blockIdx.x == 0 && blockIdx.y == 0 && threadIdx.x < HID) {
        g_sum[threadIdx.x] = 0.0f;
        g_sq[threadIdx.x] = 0.0f;
    }

    int nb = blockIdx.y;
    const float* B = ((nb < 2) ? Wf : Ws) + layer * ZDIM * HID + (nb & 1) * HID * HID;
    int m0 = blockIdx.x * 128;

    __shared__ float As[2][16][132];
    __shared__ float Bs[2][16][128];

    int tid = threadIdx.x;
    int tx = tid & 15, ty = tid >> 4;

    int arow = tid & 127;
    int akq = (tid >> 7) * 8;
    int brow = tid >> 4;
    int bcol = (tid & 15) * 8;

    float acc[8][8];
#pragma unroll
    for (int i = 0; i < 8; i++)
#pragma unroll
        for (int j = 0; j < 8; j++) acc[i][j] = 0.0f;

    int gm_a = m0 + arow;
    bool a_ok = (gm_a < N_NODES);
    const float* a_ptr = &g_h[(a_ok ? gm_a : 0) * HID + akq];

    float4 pa0 = make_float4(0.f, 0.f, 0.f, 0.f), pa1 = pa0;
    if (a_ok) { pa0 = *(const float4*)&a_ptr[0]; pa1 = *(const float4*)&a_ptr[4]; }
    float4 pb0 = *(const float4*)&B[brow * HID + bcol];
    float4 pb1 = *(const float4*)&B[brow * HID + bcol + 4];
    {
        As[0][akq + 0][arow] = pa0.x; As[0][akq + 1][arow] = pa0.y;
        As[0][akq + 2][arow] = pa0.z; As[0][akq + 3][arow] = pa0.w;
        As[0][akq + 4][arow] = pa1.x; As[0][akq + 5][arow] = pa1.y;
        As[0][akq + 6][arow] = pa1.z; As[0][akq + 7][arow] = pa1.w;
        *(float4*)&Bs[0][brow][bcol] = pb0;
        *(float4*)&Bs[0][brow][bcol + 4] = pb1;
    }
    __syncthreads();

#pragma unroll
    for (int s = 0; s < 8; s++) {
        int buf = s & 1;
        if (s < 7) {
            int k0 = (s + 1) * 16;
            pa0 = make_float4(0.f, 0.f, 0.f, 0.f); pa1 = pa0;
            if (a_ok) {
                pa0 = *(const float4*)&a_ptr[k0];
                pa1 = *(const float4*)&a_ptr[k0 + 4];
            }
            pb0 = *(const float4*)&B[(k0 + brow) * HID + bcol];
            pb1 = *(const float4*)&B[(k0 + brow) * HID + bcol + 4];
        }
#pragma unroll
        for (int k = 0; k < 16; k++) {
            float4 a0 = *(const float4*)&As[buf][k][ty * 4];
            float4 a1 = *(const float4*)&As[buf][k][64 + ty * 4];
            float4 b0 = *(const float4*)&Bs[buf][k][tx * 4];
            float4 b1 = *(const float4*)&Bs[buf][k][64 + tx * 4];
            float av[8] = {a0.x, a0.y, a0.z, a0.w, a1.x, a1.y, a1.z, a1.w};
            float bv[8] = {b0.x, b0.y, b0.z, b0.w, b1.x, b1.y, b1.z, b1.w};
#pragma unroll
            for (int i = 0; i < 8; i++)
#pragma unroll
                for (int j = 0; j < 8; j++)
                    acc[i][j] = fmaf(av[i], bv[j], acc[i][j]);
        }
        if (s < 7) {
            int nbuf = buf ^ 1;
            As[nbuf][akq + 0][arow] = pa0.x; As[nbuf][akq + 1][arow] = pa0.y;
            As[nbuf][akq + 2][arow] = pa0.z; As[nbuf][akq + 3][arow] = pa0.w;
            As[nbuf][akq + 4][arow] = pa1.x; As[nbuf][akq + 5][arow] = pa1.y;
            As[nbuf][akq + 6][arow] = pa1.z; As[nbuf][akq + 7][arow] = pa1.w;
            *(float4*)&Bs[nbuf][brow][bcol] = pb0;
            *(float4*)&Bs[nbuf][brow][bcol + 4] = pb1;
        }
        __syncthreads();
    }

    if (nb == 0 || nb == 2) {
        float* out = g_proj[nb >> 1];
#pragma unroll
        for (int i = 0; i < 4; i++) {
            int gm = m0 + ty * 4 + i;
            if (gm < N_NODES) {
                *(float4*)&out[gm * HID + tx * 4] =
                    make_float4(acc[i][0], acc[i][1], acc[i][2], acc[i][3]);
                *(float4*)&out[gm * HID + 64 + tx * 4] =
                    make_float4(acc[i][4], acc[i][5], acc[i][6], acc[i][7]);
            }
            int gm2 = m0 + 64 + ty * 4 + i;
            if (gm2 < N_NODES) {
                *(float4*)&out[gm2 * HID + tx * 4] =
                    make_float4(acc[4 + i][0], acc[4 + i][1], acc[4 + i][2], acc[4 + i][3]);
                *(float4*)&out[gm2 * HID + 64 + tx * 4] =
                    make_float4(acc[4 + i][4], acc[4 + i][5], acc[4 + i][6], acc[4 + i][7]);
            }
        }
    } else {
        float* op = g_pair + ((nb == 1) ? 0 : 1);
#pragma unroll
        for (int i = 0; i < 4; i++) {
            int gm = m0 + ty * 4 + i;
            if (gm < N_NODES) {
#pragma unroll
                for (int j = 0; j < 4; j++) {
                    op[(gm * HID + tx * 4 + j) * 2] = acc[i][j];
                    op[(gm * HID + 64 + tx * 4 + j) * 2] = acc[i][4 + j];
                }
            }
            int gm2 = m0 + 64 + ty * 4 + i;
            if (gm2 < N_NODES) {
#pragma unroll
                for (int j = 0; j < 4; j++) {
                    op[(gm2 * HID + tx * 4 + j) * 2] = acc[4 + i][j];
                    op[(gm2 * HID + 64 + tx * 4 + j) * 2] = acc[4 + i][4 + j];
                }
            }
        }
    }
}

// ------ edge aggregation: ONE node per 128-thread CTA, no barriers, no smem.
//        4 warp-LDGs/edge: src + paired-gather(LDG.64) + 2x e-row(LDG.128 fp16)
__global__ __launch_bounds__(128) void edge_agg_kernel(
    const float* __restrict__ Wf, const float* __restrict__ Ws,
    const float* __restrict__ bfb, const float* __restrict__ bsb, int layer) {
    const float* Wfl = Wf + layer * ZDIM * HID + 256 * HID;   // RBF rows
    const float* Wsl = Ws + layer * ZDIM * HID + 256 * HID;

    int node = blockIdx.x;
    int ch = threadIdx.x;                 // 0..127

    float wfr[NUM_G], wsr[NUM_G];
#pragma unroll
    for (int k = 0; k < NUM_G; k++) {
        wfr[k] = Wfl[k * HID + ch];
        wsr[k] = Wsl[k * HID + ch];
    }

    const float2* PairC = ((const float2*)g_pair) + ch;   // [node][ch] -> (Bf, Bd)
    const uint4* EH = (const uint4*)g_esh;                // 2 x uint4 per edge

    float af = g_proj[0][node * HID + ch] + bfb[layer * HID + ch];
    float as = g_proj[1][node * HID + ch] + bsb[layer * HID + ch];

    int start = g_rowptr[node], end = g_rowptr[node + 1];
    float acc = 0.0f;

    if (start < end) {
        int e_last = end - 1;
        // prime pipeline: gathers for i and i+1 in flight (clamped)
        int s0 = g_srcs[start];
        int s1 = g_srcs[min(start + 1, e_last)];
        float2 p0 = PairC[s0 * HID];
        float2 p1 = PairC[s1 * HID];
        uint4 ea = EH[start * 2];
        uint4 eb = EH[start * 2 + 1];

        for (int i = start; i < end; i++) {
            // issue gather for i+2 (clamped; garbage beyond end never consumed)
            int s2 = g_srcs[min(i + 2, e_last)];
            float2 pn = PairC[s2 * HID];
            // issue e-row load for i+1 (clamped)
            int ie = min(i + 1, e_last);
            uint4 na = EH[ie * 2];
            uint4 nb4 = EH[ie * 2 + 1];

            // compute edge i (p0 issued 2 iterations ago)
            float zf = af + p0.x, zs = as + p0.y;
#define RBF2(u, k0)                                                  \
            {                                                        \
                __half2 hh = *(const __half2*)&(u);                  \
                float2 f2 = __half22float2(hh);                      \
                zf = fmaf(f2.x, wfr[k0], zf);                        \
                zs = fmaf(f2.x, wsr[k0], zs);                        \
                zf = fmaf(f2.y, wfr[k0 + 1], zf);                    \
                zs = fmaf(f2.y, wsr[k0 + 1], zs);                    \
            }
            RBF2(ea.x, 0)  RBF2(ea.y, 2)  RBF2(ea.z, 4)  RBF2(ea.w, 6)
            RBF2(eb.x, 8)  RBF2(eb.y, 10) RBF2(eb.z, 12) RBF2(eb.w, 14)
#undef RBF2
            acc += sigm(zf) * softp(zs);

            // rotate pipeline
            p0 = p1; p1 = pn;
            ea = na; eb = nb4;
        }
    }
    g_agg[node * HID + ch] = acc;

    // BN statistics: fire-and-forget REDG per channel (no smem, no barriers)
    atomicAdd(&g_sum[ch], acc);
    atomicAdd(&g_sq[ch], acc * acc);
}

// ------------------------- BN + residual + LN + ReLU + residual --------------
__global__ __launch_bounds__(256) void bn_ln_kernel(
    const float* __restrict__ bn_g, const float* __restrict__ bn_b,
    const float* __restrict__ ln_g, const float* __restrict__ ln_b, int layer) {
    __shared__ __align__(16) float sA[HID];
    __shared__ __align__(16) float sB[HID];
    int tid = threadIdx.x;
    if (tid < HID) {
        const float inv = 1.0f / (float)N_NODES;
        float mu = g_sum[tid] * inv;
        float var = g_sq[tid] * inv - mu * mu;
        float rs = rsqrtf(var + 1e-5f);
        float a = rs * bn_g[layer * HID + tid];
        sA[tid] = a;
        sB[tid] = bn_b[layer * HID + tid] - mu * a;
    }
    __syncthreads();

    int warp = tid >> 5, lane = tid & 31;
    int node = blockIdx.x * 8 + warp;
    int ch0 = lane * 4;

    float4 ag = *(const float4*)&g_agg[node * HID + ch0];
    float4 h4 = *(const float4*)&g_h[node * HID + ch0];
    float4 a4 = *(const float4*)&sA[ch0];
    float4 b4 = *(const float4*)&sB[ch0];

    float c0 = fmaf(ag.x, a4.x, b4.x) + h4.x;
    float c1 = fmaf(ag.y, a4.y, b4.y) + h4.y;
    float c2 = fmaf(ag.z, a4.z, b4.z) + h4.z;
    float c3 = fmaf(ag.w, a4.w, b4.w) + h4.w;

    float s = warp_sum(c0 + c1 + c2 + c3);
    float mean = s * (1.0f / HID);
    float sq = warp_sum(c0 * c0 + c1 * c1 + c2 * c2 + c3 * c3);
    float var = sq * (1.0f / HID) - mean * mean;
    float rs = rsqrtf(var + 1e-5f);

    float4 lg = *(const float4*)&ln_g[layer * HID + ch0];
    float4 lb = *(const float4*)&ln_b[layer * HID + ch0];

    float r0 = fmaxf(fmaf((c0 - mean) * rs, lg.x, lb.x), 0.0f) + h4.x;
    float r1 = fmaxf(fmaf((c1 - mean) * rs, lg.y, lb.y), 0.0f) + h4.y;
    float r2 = fmaxf(fmaf((c2 - mean) * rs, lg.z, lb.z), 0.0f) + h4.z;
    float r3 = fmaxf(fmaf((c3 - mean) * rs, lg.w, lb.w), 0.0f) + h4.w;

    *(float4*)&g_h[node * HID + ch0] = make_float4(r0, r1, r2, r3);
}

// ------------------------- final LN + FC -------------------------------------
__global__ __launch_bounds__(256) void final_kernel(
    const float* __restrict__ lng, const float* __restrict__ lnb,
    const float* __restrict__ Wfc, const float* __restrict__ bfc,
    float* __restrict__ out) {
    int warp = threadIdx.x >> 5, lane = threadIdx.x & 31;
    int node = blockIdx.x * 8 + warp;
    int ch0 = lane * 4;

    float4 h4 = *(const float4*)&g_h[node * HID + ch0];
    float s = warp_sum(h4.x + h4.y + h4.z + h4.w);
    float mean = s * (1.0f / HID);
    float sq = warp_sum(h4.x * h4.x + h4.y * h4.y + h4.z * h4.z + h4.w * h4.w);
    float var = sq * (1.0f / HID) - mean * mean;
    float rs = rsqrtf(var + 1e-5f);

    float4 lg = *(const float4*)&lng[ch0];
    float4 lb = *(const float4*)&lnb[ch0];
    float hn0 = fmaf((h4.x - mean) * rs, lg.x, lb.x);
    float hn1 = fmaf((h4.y - mean) * rs, lg.y, lb.y);
    float hn2 = fmaf((h4.z - mean) * rs, lg.z, lb.z);
    float hn3 = fmaf((h4.w - mean) * rs, lg.w, lb.w);

#pragma unroll
    for (int j = 0; j < N_CLS; j++) {
        float p = hn0 * Wfc[(ch0 + 0) * N_CLS + j]
                + hn1 * Wfc[(ch0 + 1) * N_CLS + j]
                + hn2 * Wfc[(ch0 + 2) * N_CLS + j]
                + hn3 * Wfc[(ch0 + 3) * N_CLS + j];
        p = warp_sum(p);
        if (lane == 0) out[node * N_CLS + j] = p + bfc[j];
    }
}

// ------------------------- launch -------------------------------------------
extern "C" void kernel_launch(void* const* d_in, const int* in_sizes, int n_in,
                              void* d_out, int out_size) {
    const float* x        = (const float*)d_in[0];
    const int*   ei       = (const int*)d_in[1];
    const float* dist     = (const float*)d_in[2];
    const float* W_node   = (const float*)d_in[3];
    const float* b_node   = (const float*)d_in[4];
    const float* Wf       = (const float*)d_in[5];
    const float* bf       = (const float*)d_in[6];
    const float* Ws       = (const float*)d_in[7];
    const float* bs       = (const float*)d_in[8];
    const float* bn_g     = (const float*)d_in[9];
    const float* bn_b     = (const float*)d_in[10];
    const float* ln_g     = (const float*)d_in[11];
    const float* ln_b     = (const float*)d_in[12];
    const float* lnout_g  = (const float*)d_in[13];
    const float* lnout_b  = (const float*)d_in[14];
    const float* W_fc     = (const float*)d_in[15];
    const float* b_fc     = (const float*)d_in[16];
    float* out = (float*)d_out;

    setup_kernel<<<(N_NODES * HID + 255) / 256, 256>>>(x, W_node, b_node);   // 1
    count_kernel<<<(N_EDGES + 255) / 256, 256>>>(ei);                        // 2
    scan_kernel<<<1, 1024>>>();                                              // 3
    gemm_node_kernel<<<dim3(157, 4), 256>>>(Wf, Ws, 0);                      // 4
    rbf_scatter_kernel<<<(N_EDGES + 255) / 256, 256>>>(dist, ei);            // 5
    edge_agg_kernel<<<N_NODES, 128>>>(Wf, Ws, bf, bs, 0);                    // 6
    bn_ln_kernel<<<N_NODES / 8, 256>>>(bn_g, bn_b, ln_g, ln_b, 0);           // 7

    for (int l = 1; l < N_LAYERS; l++) {
        gemm_node_kernel<<<dim3(157, 4), 256>>>(Wf, Ws, l);
        edge_agg_kernel<<<N_NODES, 128>>>(Wf, Ws, bf, bs, l);
        bn_ln_kernel<<<N_NODES / 8, 256>>>(bn_g, bn_b, ln_g, ln_b, l);
    }

    final_kernel<<<N_NODES / 8, 256>>>(lnout_g, lnout_b, W_fc, b_fc, out);
}